// round 2
// baseline (speedup 1.0000x reference)
#include <cuda_runtime.h>
#include <cuda_bf16.h>

#define N_NODES 1024
#define E_EDGES 16384
#define IN_DIM  1300
#define H_HEADS 16
#define D_HEAD  512
#define F_DIM   8192        // H_HEADS * D_HEAD
#define G_GRAPHS 8
#define ET (E_EDGES + N_NODES)   // 17408 edges incl. self loops
#define SLOPE 0.2f

// ---------------- scratch (device globals; no runtime allocation) ----------
__device__ float g_h[N_NODES * F_DIM];      // GEMM output of current layer (32 MB)
__device__ float g_agg[N_NODES * F_DIM];    // aggregated (relu'd) layer output (32 MB)
__device__ float g_ssrc[N_NODES * H_HEADS];
__device__ float g_sdst[N_NODES * H_HEADS];
__device__ int   g_src[ET];
__device__ int   g_dst[ET];
__device__ int   g_cnt[N_NODES];
__device__ int   g_off[N_NODES + 1];
__device__ int   g_cur[N_NODES];
__device__ int   g_csr_src[ET];
__device__ float g_alpha[ET * H_HEADS];
__device__ float g_nodeval[N_NODES];

// ---------------- GEMM: C[M,N] = A[M,K] @ B[K,N], fp32, 128x128x8 tiles ----
// M=1024 (mult of 128), N=8192 (mult of 128); K arbitrary (guarded).
__global__ __launch_bounds__(256) void sgemm128(
    const float* __restrict__ A, const float* __restrict__ B,
    float* __restrict__ C, int M, int N, int K)
{
    __shared__ float As[8][128];
    __shared__ float Bs[8][128];

    const int tid = threadIdx.x;
    const int bm = blockIdx.y, bn = blockIdx.x;
    const int tx = tid & 15;        // 0..15  -> 8 cols each
    const int ty = tid >> 4;        // 0..15  -> 8 rows each

    const int aRow = tid >> 1;            // 0..127
    const int aCol = (tid & 1) * 4;       // 0 or 4
    const int bRow = tid >> 5;            // 0..7
    const int bCol = (tid & 31) * 4;      // 0..124

    const float* Aptr = A + (size_t)(bm * 128 + aRow) * K;
    const float* Bbase = B + (size_t)bn * 128 + bCol;

    float acc[8][8];
    #pragma unroll
    for (int i = 0; i < 8; i++)
        #pragma unroll
        for (int j = 0; j < 8; j++) acc[i][j] = 0.f;

    for (int k0 = 0; k0 < K; k0 += 8) {
        // load A tile (128x8), transposed into As[k][m]
        float4 av;
        if (k0 + 8 <= K) {
            av = *(const float4*)(Aptr + k0 + aCol);
        } else {
            av.x = (k0 + aCol + 0 < K) ? Aptr[k0 + aCol + 0] : 0.f;
            av.y = (k0 + aCol + 1 < K) ? Aptr[k0 + aCol + 1] : 0.f;
            av.z = (k0 + aCol + 2 < K) ? Aptr[k0 + aCol + 2] : 0.f;
            av.w = (k0 + aCol + 3 < K) ? Aptr[k0 + aCol + 3] : 0.f;
        }
        As[aCol + 0][aRow] = av.x;
        As[aCol + 1][aRow] = av.y;
        As[aCol + 2][aRow] = av.z;
        As[aCol + 3][aRow] = av.w;

        // load B tile (8x128)
        float4 bv = make_float4(0.f, 0.f, 0.f, 0.f);
        if (k0 + bRow < K)
            bv = *(const float4*)(Bbase + (size_t)(k0 + bRow) * N);
        *(float4*)&Bs[bRow][bCol] = bv;

        __syncthreads();

        #pragma unroll
        for (int kk = 0; kk < 8; kk++) {
            float ra[8], rb[8];
            float4 a0 = *(const float4*)&As[kk][ty * 8];
            float4 a1 = *(const float4*)&As[kk][ty * 8 + 4];
            float4 b0 = *(const float4*)&Bs[kk][tx * 8];
            float4 b1 = *(const float4*)&Bs[kk][tx * 8 + 4];
            ra[0] = a0.x; ra[1] = a0.y; ra[2] = a0.z; ra[3] = a0.w;
            ra[4] = a1.x; ra[5] = a1.y; ra[6] = a1.z; ra[7] = a1.w;
            rb[0] = b0.x; rb[1] = b0.y; rb[2] = b0.z; rb[3] = b0.w;
            rb[4] = b1.x; rb[5] = b1.y; rb[6] = b1.z; rb[7] = b1.w;
            #pragma unroll
            for (int i = 0; i < 8; i++)
                #pragma unroll
                for (int j = 0; j < 8; j++)
                    acc[i][j] += ra[i] * rb[j];
        }
        __syncthreads();
    }

    // write back
    #pragma unroll
    for (int i = 0; i < 8; i++) {
        int row = bm * 128 + ty * 8 + i;
        float* cp = C + (size_t)row * N + bn * 128 + tx * 8;
        float4 c0 = make_float4(acc[i][0], acc[i][1], acc[i][2], acc[i][3]);
        float4 c1 = make_float4(acc[i][4], acc[i][5], acc[i][6], acc[i][7]);
        *(float4*)(cp + 0) = c0;
        *(float4*)(cp + 4) = c1;
    }
}

// ---------------- attention scores: s_src/s_dst [N,H] -----------------------
__global__ void scores_kernel(const float* __restrict__ h,
                              const float* __restrict__ asrc,
                              const float* __restrict__ adst)
{
    int n = blockIdx.x;
    int w = threadIdx.x >> 5;       // head = warp id (16 warps)
    int lane = threadIdx.x & 31;
    const float* hp = h + (size_t)n * F_DIM + w * D_HEAD;
    const float* ap = asrc + w * D_HEAD;
    const float* bp = adst + w * D_HEAD;
    float s1 = 0.f, s2 = 0.f;
    #pragma unroll 4
    for (int d = lane; d < D_HEAD; d += 32) {
        float v = hp[d];
        s1 += v * ap[d];
        s2 += v * bp[d];
    }
    #pragma unroll
    for (int o = 16; o; o >>= 1) {
        s1 += __shfl_down_sync(0xffffffffu, s1, o);
        s2 += __shfl_down_sync(0xffffffffu, s2, o);
    }
    if (lane == 0) {
        g_ssrc[n * H_HEADS + w] = s1;
        g_sdst[n * H_HEADS + w] = s2;
    }
}

// ---------------- CSR build over dst ---------------------------------------
__global__ void zero_cnt_kernel() { g_cnt[threadIdx.x] = 0; }

__global__ void build_edges_kernel(const int* __restrict__ ei)
{
    int e = blockIdx.x * blockDim.x + threadIdx.x;
    if (e >= ET) return;
    int s, d;
    if (e < E_EDGES) { s = ei[e]; d = ei[E_EDGES + e]; }
    else             { s = e - E_EDGES; d = s; }
    g_src[e] = s;
    g_dst[e] = d;
    atomicAdd(&g_cnt[d], 1);
}

__global__ void scan_kernel()
{
    __shared__ int sm[N_NODES];
    int t = threadIdx.x;
    sm[t] = g_cnt[t];
    __syncthreads();
    for (int o = 1; o < N_NODES; o <<= 1) {
        int v = (t >= o) ? sm[t - o] : 0;
        __syncthreads();
        sm[t] += v;
        __syncthreads();
    }
    g_off[t + 1] = sm[t];
    int excl = (t == 0) ? 0 : sm[t - 1];
    if (t == 0) g_off[0] = 0;
    g_cur[t] = excl;
}

__global__ void scatter_kernel()
{
    int e = blockIdx.x * blockDim.x + threadIdx.x;
    if (e >= ET) return;
    int d = g_dst[e];
    int p = atomicAdd(&g_cur[d], 1);
    g_csr_src[p] = g_src[e];
}

// ---------------- segment softmax per (dst, head) ---------------------------
__global__ void attn_kernel()
{
    int n = blockIdx.x;
    int h = threadIdx.x >> 5;       // 16 warps = 16 heads
    int lane = threadIdx.x & 31;
    int beg = g_off[n], end = g_off[n + 1];
    float sd = g_sdst[n * H_HEADS + h];

    float mx = -1e30f;
    for (int p = beg + lane; p < end; p += 32) {
        float e = g_ssrc[g_csr_src[p] * H_HEADS + h] + sd;
        e = (e > 0.f) ? e : SLOPE * e;
        mx = fmaxf(mx, e);
    }
    #pragma unroll
    for (int o = 16; o; o >>= 1)
        mx = fmaxf(mx, __shfl_xor_sync(0xffffffffu, mx, o));

    float sum = 0.f;
    for (int p = beg + lane; p < end; p += 32) {
        float e = g_ssrc[g_csr_src[p] * H_HEADS + h] + sd;
        e = (e > 0.f) ? e : SLOPE * e;
        float pv = __expf(e - mx);
        g_alpha[p * H_HEADS + h] = pv;
        sum += pv;
    }
    #pragma unroll
    for (int o = 16; o; o >>= 1)
        sum += __shfl_xor_sync(0xffffffffu, sum, o);

    float inv = 1.f / sum;
    for (int p = beg + lane; p < end; p += 32)
        g_alpha[p * H_HEADS + h] *= inv;
}

// ---------------- aggregation: out[n] = relu(sum_e alpha * h[src] + b) ------
__global__ __launch_bounds__(256) void agg_kernel(
    const float* __restrict__ hin, const float* __restrict__ bias,
    float* __restrict__ out)
{
    int n = blockIdx.x;
    int tid = threadIdx.x;          // 256 threads, float4 each: 8 chunks
    int hi = tid >> 7;              // 0/1 : which half of a head pair
    int beg = g_off[n], end = g_off[n + 1];

    float4 acc[8];
    #pragma unroll
    for (int j = 0; j < 8; j++) acc[j] = make_float4(0.f, 0.f, 0.f, 0.f);

    for (int p = beg; p < end; p++) {
        int s = g_csr_src[p];
        const float4* hrow = (const float4*)(hin + (size_t)s * F_DIM);
        const float* al = &g_alpha[p * H_HEADS];
        #pragma unroll
        for (int j = 0; j < 8; j++) {
            // element base = j*1024 + tid*4 -> head = 2*j + (tid>>7)
            float a = al[2 * j + hi];
            float4 v = hrow[j * 256 + tid];
            acc[j].x += a * v.x;
            acc[j].y += a * v.y;
            acc[j].z += a * v.z;
            acc[j].w += a * v.w;
        }
    }

    const float4* b4 = (const float4*)bias;
    float4* o4 = (float4*)(out + (size_t)n * F_DIM);
    #pragma unroll
    for (int j = 0; j < 8; j++) {
        int idx = j * 256 + tid;
        float4 b = b4[idx];
        float4 r;
        r.x = fmaxf(acc[j].x + b.x, 0.f);
        r.y = fmaxf(acc[j].y + b.y, 0.f);
        r.z = fmaxf(acc[j].z + b.z, 0.f);
        r.w = fmaxf(acc[j].w + b.w, 0.f);
        o4[idx] = r;
    }
}

// ---------------- per-node linear + pooled output ---------------------------
__global__ void nodedot_kernel(const float* __restrict__ hin,
                               const float* __restrict__ w)
{
    int n = blockIdx.x;
    int t = threadIdx.x;            // 256
    const float* hp = hin + (size_t)n * F_DIM;
    float s = 0.f;
    #pragma unroll 4
    for (int i = t; i < F_DIM; i += 256) s += hp[i] * w[i];
    __shared__ float sm[256];
    sm[t] = s;
    __syncthreads();
    for (int o = 128; o; o >>= 1) {
        if (t < o) sm[t] += sm[t + o];
        __syncthreads();
    }
    if (t == 0) g_nodeval[n] = sm[0];
}

__global__ void pool_kernel(const int* __restrict__ batch,
                            const float* __restrict__ lin_b,
                            float* __restrict__ out)
{
    __shared__ float ssum[G_GRAPHS];
    __shared__ int scnt[G_GRAPHS];
    int t = threadIdx.x;            // 1024
    if (t < G_GRAPHS) { ssum[t] = 0.f; scnt[t] = 0; }
    __syncthreads();
    int g = batch[t];
    atomicAdd(&ssum[g], g_nodeval[t]);
    atomicAdd(&scnt[g], 1);
    __syncthreads();
    if (t < G_GRAPHS)
        out[t] = ssum[t] / fmaxf((float)scnt[t], 1.0f) + lin_b[0];
}

// ---------------- launch ----------------------------------------------------
extern "C" void kernel_launch(void* const* d_in, const int* in_sizes, int n_in,
                              void* d_out, int out_size)
{
    const float* x   = (const float*)d_in[0];
    const int*   ei  = (const int*)d_in[1];
    const int*   bat = (const int*)d_in[2];
    const float* W1  = (const float*)d_in[3];
    const float* as1 = (const float*)d_in[4];
    const float* ad1 = (const float*)d_in[5];
    const float* b1  = (const float*)d_in[6];
    const float* W2  = (const float*)d_in[7];
    const float* as2 = (const float*)d_in[8];
    const float* ad2 = (const float*)d_in[9];
    const float* b2  = (const float*)d_in[10];
    const float* lw  = (const float*)d_in[11];
    const float* lb  = (const float*)d_in[12];
    float* out = (float*)d_out;

    float *p_h = nullptr, *p_agg = nullptr;
    cudaGetSymbolAddress((void**)&p_h, g_h);
    cudaGetSymbolAddress((void**)&p_agg, g_agg);

    const int ethreads = 256;
    const int eblocks = (ET + ethreads - 1) / ethreads;

    // CSR over dst (rebuilt each call; cheap, graph-capturable, resets state)
    zero_cnt_kernel<<<1, N_NODES>>>();
    build_edges_kernel<<<eblocks, ethreads>>>(ei);
    scan_kernel<<<1, N_NODES>>>();
    scatter_kernel<<<eblocks, ethreads>>>();

    dim3 ggrid(F_DIM / 128, N_NODES / 128);   // 64 x 8

    // ---- layer 1 ----
    sgemm128<<<ggrid, 256>>>(x, W1, p_h, N_NODES, F_DIM, IN_DIM);
    scores_kernel<<<N_NODES, 512>>>(p_h, as1, ad1);
    attn_kernel<<<N_NODES, 512>>>();
    agg_kernel<<<N_NODES, 256>>>(p_h, b1, p_agg);

    // ---- layer 2 ----
    sgemm128<<<ggrid, 256>>>(p_agg, W2, p_h, N_NODES, F_DIM, F_DIM);
    scores_kernel<<<N_NODES, 512>>>(p_h, as2, ad2);
    attn_kernel<<<N_NODES, 512>>>();
    agg_kernel<<<N_NODES, 256>>>(p_h, b2, p_agg);

    // ---- readout ----
    nodedot_kernel<<<N_NODES, 256>>>(p_agg, lw);
    pool_kernel<<<1, N_NODES>>>(bat, lb, out);
}

// round 6
// speedup vs baseline: 2.6125x; 2.6125x over previous
#include <cuda_runtime.h>
#include <cuda_bf16.h>
#include <cstdint>

#define N_NODES 1024
#define E_EDGES 16384
#define IN_DIM  1300
#define H_HEADS 16
#define D_HEAD  512
#define F_DIM   8192
#define G_GRAPHS 8
#define ET (E_EDGES + N_NODES)
#define SLOPE 0.2f

#define KP1 1344              // IN_DIM padded to multiple of 32

// ---------------- scratch ----------------------------------------------------
__device__ float g_h[N_NODES * F_DIM];
__device__ float g_agg[N_NODES * F_DIM];
__device__ float g_ssrc[N_NODES * H_HEADS];
__device__ float g_sdst[N_NODES * H_HEADS];
__device__ int   g_src[ET];
__device__ int   g_dst[ET];
__device__ int   g_cnt[N_NODES];
__device__ int   g_off[N_NODES + 1];
__device__ int   g_cur[N_NODES];
__device__ int   g_csr_src[ET];
__device__ float g_alpha[ET * H_HEADS];
__device__ float g_nodeval[N_NODES];
// bf16 split buffers (reused by both layers)
__device__ __nv_bfloat16 g_Ah[N_NODES * F_DIM];
__device__ __nv_bfloat16 g_Al[N_NODES * F_DIM];
__device__ __nv_bfloat16 g_Bth[(size_t)F_DIM * F_DIM];
__device__ __nv_bfloat16 g_Btl[(size_t)F_DIM * F_DIM];

// ---------------- PTX helpers ------------------------------------------------
__device__ __forceinline__ uint32_t smem_u32(const void* p) {
    uint32_t a;
    asm("{ .reg .u64 t; cvta.to.shared.u64 t, %1; cvt.u32.u64 %0, t; }" : "=r"(a) : "l"(p));
    return a;
}
__device__ __forceinline__ void cp16(uint32_t dst, const void* src) {
    asm volatile("cp.async.cg.shared.global [%0], [%1], 16;\n" :: "r"(dst), "l"(src) : "memory");
}
__device__ __forceinline__ void cp_commit() {
    asm volatile("cp.async.commit_group;\n" ::: "memory");
}
__device__ __forceinline__ void cp_wait0() { asm volatile("cp.async.wait_group 0;\n" ::: "memory"); }
__device__ __forceinline__ void cp_wait2() { asm volatile("cp.async.wait_group 2;\n" ::: "memory"); }

__device__ __forceinline__ void mma_bf16(float* c, const uint32_t* a, uint32_t b0, uint32_t b1) {
    asm volatile(
        "mma.sync.aligned.m16n8k16.row.col.f32.bf16.bf16.f32 "
        "{%0,%1,%2,%3}, {%4,%5,%6,%7}, {%8,%9}, {%0,%1,%2,%3};\n"
        : "+f"(c[0]), "+f"(c[1]), "+f"(c[2]), "+f"(c[3])
        : "r"(a[0]), "r"(a[1]), "r"(a[2]), "r"(a[3]), "r"(b0), "r"(b1));
}

__device__ __forceinline__ uint32_t lds32(uint32_t addr) {
    uint32_t v;
    asm volatile("ld.shared.b32 %0, [%1];" : "=r"(v) : "r"(addr));
    return v;
}

// fragment address within an 8KB [128 rows][32 bf16] tile with 16B-chunk XOR swizzle
__device__ __forceinline__ uint32_t frag_off(int row, int c, int t) {
    return (uint32_t)(row * 64 + ((c ^ ((row >> 1) & 3)) << 4) + (t << 2));
}

// ---------------- conversion kernels -----------------------------------------
__global__ void convA_kernel(const float* __restrict__ A, int K, int Kp,
                             __nv_bfloat16* __restrict__ Ah, __nv_bfloat16* __restrict__ Al)
{
    int row = blockIdx.y;
    int col = blockIdx.x * 256 + threadIdx.x;
    if (col >= Kp) return;
    float v = (col < K) ? A[(size_t)row * K + col] : 0.f;
    __nv_bfloat16 h = __float2bfloat16(v);
    float r = v - __bfloat162float(h);
    size_t o = (size_t)row * Kp + col;
    Ah[o] = h;
    Al[o] = __float2bfloat16(r);
}

// B [K, F_DIM] fp32 -> Bt_hi/lo [F_DIM, Kp] bf16 (transposed, zero-padded in K)
__global__ void convBt_kernel(const float* __restrict__ B, int K, int Kp,
                              __nv_bfloat16* __restrict__ Bth, __nv_bfloat16* __restrict__ Btl)
{
    __shared__ float sm[32][33];
    int k0 = blockIdx.x * 32, n0 = blockIdx.y * 32;
    int tx = threadIdx.x, ty = threadIdx.y;
    int k = k0 + ty;
    sm[ty][tx] = (k < K) ? B[(size_t)k * F_DIM + n0 + tx] : 0.f;
    __syncthreads();
    float v = sm[tx][ty];
    __nv_bfloat16 h = __float2bfloat16(v);
    size_t o = (size_t)(n0 + ty) * Kp + k0 + tx;
    Bth[o] = h;
    Btl[o] = __float2bfloat16(v - __bfloat162float(h));
}

// ---------------- mma.sync GEMM: C[1024, 8192] = A[1024,Kp] @ Bt[8192,Kp]^T ---
// CTA tile 128x128, K-chunk 32, 3 pipeline stages.
// Stage layout (32KB): Ah[0,8K) Al[8K,16K) Bh[16K,24K) Bl[24K,32K)
#define STAGE_SZ 32768u
#define NSTAGE 3
#define GEMM_SMEM (STAGE_SZ * NSTAGE)

__global__ __launch_bounds__(256, 2) void mma_gemm_kernel(
    const __nv_bfloat16* __restrict__ Ah, const __nv_bfloat16* __restrict__ Al,
    const __nv_bfloat16* __restrict__ Bh, const __nv_bfloat16* __restrict__ Bl,
    float* __restrict__ C, int Kp, int nc)
{
    extern __shared__ __align__(128) char smem[];
    const uint32_t sb = smem_u32(smem);
    const int tid = threadIdx.x;
    const int wid = tid >> 5;
    const int lane = tid & 31;
    const int g = lane >> 2;       // 0..7
    const int t = lane & 3;        // 0..3
    const int wm = (wid >> 2) * 64;
    const int wn = (wid & 3) * 32;
    const int m0 = blockIdx.y * 128;
    const int n0 = blockIdx.x * 128;

    const __nv_bfloat16* aH = Ah + (size_t)m0 * Kp;
    const __nv_bfloat16* aL = Al + (size_t)m0 * Kp;
    const __nv_bfloat16* bH = Bh + (size_t)n0 * Kp;
    const __nv_bfloat16* bL = Bl + (size_t)n0 * Kp;

    float acc[4][4][4];
    #pragma unroll
    for (int i = 0; i < 4; i++)
        #pragma unroll
        for (int j = 0; j < 4; j++)
            #pragma unroll
            for (int q = 0; q < 4; q++) acc[i][j][q] = 0.f;

    // per-thread load coords: 512 cp16 units per 8KB tile, 2 per thread
    const int r_u0 = tid >> 2,        ch_u0 = tid & 3;
    const int r_u1 = (tid + 256) >> 2, ch_u1 = (tid + 256) & 3;
    const uint32_t so0 = (uint32_t)(r_u0 * 64 + ((ch_u0 ^ ((r_u0 >> 1) & 3)) << 4));
    const uint32_t so1 = (uint32_t)(r_u1 * 64 + ((ch_u1 ^ ((r_u1 >> 1) & 3)) << 4));

    auto load_stage = [&](int c, int st) {
        const uint32_t base = sb + (uint32_t)st * STAGE_SZ;
        const int kc0 = c * 32;
        const size_t go0 = (size_t)r_u0 * Kp + kc0 + ch_u0 * 8;
        const size_t go1 = (size_t)r_u1 * Kp + kc0 + ch_u1 * 8;
        cp16(base + so0,          aH + go0);
        cp16(base + so1,          aH + go1);
        cp16(base + 8192 + so0,   aL + go0);
        cp16(base + 8192 + so1,   aL + go1);
        cp16(base + 16384 + so0,  bH + go0);
        cp16(base + 16384 + so1,  bH + go1);
        cp16(base + 24576 + so0,  bL + go0);
        cp16(base + 24576 + so1,  bL + go1);
        cp_commit();
    };

    load_stage(0, 0);
    if (nc > 1) load_stage(1, 1);

    for (int c = 0; c < nc; c++) {
        const int st = c % NSTAGE;
        if (c + 2 < nc) {
            load_stage(c + 2, (c + 2) % NSTAGE);
            cp_wait2();
        } else {
            cp_wait0();
        }
        __syncthreads();

        const uint32_t base = sb + (uint32_t)st * STAGE_SZ;
        #pragma unroll
        for (int s = 0; s < 2; s++) {
            uint32_t Af[4][4], Alf[4][4];
            #pragma unroll
            for (int i = 0; i < 4; i++) {
                const int r0 = wm + i * 16 + g;
                const int r1 = r0 + 8;
                Af[i][0]  = lds32(base + frag_off(r0, s * 2,     t));
                Af[i][1]  = lds32(base + frag_off(r1, s * 2,     t));
                Af[i][2]  = lds32(base + frag_off(r0, s * 2 + 1, t));
                Af[i][3]  = lds32(base + frag_off(r1, s * 2 + 1, t));
                Alf[i][0] = lds32(base + 8192 + frag_off(r0, s * 2,     t));
                Alf[i][1] = lds32(base + 8192 + frag_off(r1, s * 2,     t));
                Alf[i][2] = lds32(base + 8192 + frag_off(r0, s * 2 + 1, t));
                Alf[i][3] = lds32(base + 8192 + frag_off(r1, s * 2 + 1, t));
            }
            #pragma unroll
            for (int j = 0; j < 4; j++) {
                const int n = wn + j * 8 + g;
                const uint32_t bh0 = lds32(base + 16384 + frag_off(n, s * 2,     t));
                const uint32_t bh1 = lds32(base + 16384 + frag_off(n, s * 2 + 1, t));
                const uint32_t bl0 = lds32(base + 24576 + frag_off(n, s * 2,     t));
                const uint32_t bl1 = lds32(base + 24576 + frag_off(n, s * 2 + 1, t));
                #pragma unroll
                for (int i = 0; i < 4; i++) {
                    mma_bf16(acc[i][j], Af[i],  bh0, bh1);
                    mma_bf16(acc[i][j], Alf[i], bh0, bh1);
                    mma_bf16(acc[i][j], Af[i],  bl0, bl1);
                }
            }
        }
        __syncthreads();
    }

    // epilogue
    #pragma unroll
    for (int i = 0; i < 4; i++) {
        const int row0 = m0 + wm + i * 16 + g;
        #pragma unroll
        for (int j = 0; j < 4; j++) {
            const int col = n0 + wn + j * 8 + t * 2;
            float2* p0 = (float2*)(C + (size_t)row0 * F_DIM + col);
            float2* p1 = (float2*)(C + (size_t)(row0 + 8) * F_DIM + col);
            *p0 = make_float2(acc[i][j][0], acc[i][j][1]);
            *p1 = make_float2(acc[i][j][2], acc[i][j][3]);
        }
    }
}

// ---------------- attention scores ------------------------------------------
__global__ void scores_kernel(const float* __restrict__ h,
                              const float* __restrict__ asrc,
                              const float* __restrict__ adst)
{
    int n = blockIdx.x;
    int w = threadIdx.x >> 5;
    int lane = threadIdx.x & 31;
    const float* hp = h + (size_t)n * F_DIM + w * D_HEAD;
    const float* ap = asrc + w * D_HEAD;
    const float* bp = adst + w * D_HEAD;
    float s1 = 0.f, s2 = 0.f;
    #pragma unroll 4
    for (int d = lane; d < D_HEAD; d += 32) {
        float v = hp[d];
        s1 += v * ap[d];
        s2 += v * bp[d];
    }
    #pragma unroll
    for (int o = 16; o; o >>= 1) {
        s1 += __shfl_down_sync(0xffffffffu, s1, o);
        s2 += __shfl_down_sync(0xffffffffu, s2, o);
    }
    if (lane == 0) {
        g_ssrc[n * H_HEADS + w] = s1;
        g_sdst[n * H_HEADS + w] = s2;
    }
}

// ---------------- CSR build over dst -----------------------------------------
__global__ void zero_cnt_kernel() { g_cnt[threadIdx.x] = 0; }

__global__ void build_edges_kernel(const int* __restrict__ ei)
{
    int e = blockIdx.x * blockDim.x + threadIdx.x;
    if (e >= ET) return;
    int s, d;
    if (e < E_EDGES) { s = ei[e]; d = ei[E_EDGES + e]; }
    else             { s = e - E_EDGES; d = s; }
    g_src[e] = s;
    g_dst[e] = d;
    atomicAdd(&g_cnt[d], 1);
}

__global__ void scan_kernel()
{
    __shared__ int sm[N_NODES];
    int t = threadIdx.x;
    sm[t] = g_cnt[t];
    __syncthreads();
    for (int o = 1; o < N_NODES; o <<= 1) {
        int v = (t >= o) ? sm[t - o] : 0;
        __syncthreads();
        sm[t] += v;
        __syncthreads();
    }
    g_off[t + 1] = sm[t];
    int excl = (t == 0) ? 0 : sm[t - 1];
    if (t == 0) g_off[0] = 0;
    g_cur[t] = excl;
}

__global__ void scatter_kernel()
{
    int e = blockIdx.x * blockDim.x + threadIdx.x;
    if (e >= ET) return;
    int d = g_dst[e];
    int p = atomicAdd(&g_cur[d], 1);
    g_csr_src[p] = g_src[e];
}

// ---------------- segment softmax per (dst, head) ----------------------------
__global__ void attn_kernel()
{
    int n = blockIdx.x;
    int h = threadIdx.x >> 5;
    int lane = threadIdx.x & 31;
    int beg = g_off[n], end = g_off[n + 1];
    float sd = g_sdst[n * H_HEADS + h];

    float mx = -1e30f;
    for (int p = beg + lane; p < end; p += 32) {
        float e = g_ssrc[g_csr_src[p] * H_HEADS + h] + sd;
        e = (e > 0.f) ? e : SLOPE * e;
        mx = fmaxf(mx, e);
    }
    #pragma unroll
    for (int o = 16; o; o >>= 1)
        mx = fmaxf(mx, __shfl_xor_sync(0xffffffffu, mx, o));

    float sum = 0.f;
    for (int p = beg + lane; p < end; p += 32) {
        float e = g_ssrc[g_csr_src[p] * H_HEADS + h] + sd;
        e = (e > 0.f) ? e : SLOPE * e;
        float pv = __expf(e - mx);
        g_alpha[p * H_HEADS + h] = pv;
        sum += pv;
    }
    #pragma unroll
    for (int o = 16; o; o >>= 1)
        sum += __shfl_xor_sync(0xffffffffu, sum, o);

    float inv = 1.f / sum;
    for (int p = beg + lane; p < end; p += 32)
        g_alpha[p * H_HEADS + h] *= inv;
}

// ---------------- aggregation -------------------------------------------------
__global__ __launch_bounds__(256) void agg_kernel(
    const float* __restrict__ hin, const float* __restrict__ bias,
    float* __restrict__ out)
{
    int n = blockIdx.x;
    int tid = threadIdx.x;
    int hi = tid >> 7;
    int beg = g_off[n], end = g_off[n + 1];

    float4 acc[8];
    #pragma unroll
    for (int j = 0; j < 8; j++) acc[j] = make_float4(0.f, 0.f, 0.f, 0.f);

    for (int p = beg; p < end; p++) {
        int s = g_csr_src[p];
        const float4* hrow = (const float4*)(hin + (size_t)s * F_DIM);
        const float* al = &g_alpha[p * H_HEADS];
        #pragma unroll
        for (int j = 0; j < 8; j++) {
            float a = al[2 * j + hi];
            float4 v = hrow[j * 256 + tid];
            acc[j].x += a * v.x;
            acc[j].y += a * v.y;
            acc[j].z += a * v.z;
            acc[j].w += a * v.w;
        }
    }

    const float4* b4 = (const float4*)bias;
    float4* o4 = (float4*)(out + (size_t)n * F_DIM);
    #pragma unroll
    for (int j = 0; j < 8; j++) {
        int idx = j * 256 + tid;
        float4 b = b4[idx];
        float4 r;
        r.x = fmaxf(acc[j].x + b.x, 0.f);
        r.y = fmaxf(acc[j].y + b.y, 0.f);
        r.z = fmaxf(acc[j].z + b.z, 0.f);
        r.w = fmaxf(acc[j].w + b.w, 0.f);
        o4[idx] = r;
    }
}

// ---------------- readout ------------------------------------------------------
__global__ void nodedot_kernel(const float* __restrict__ hin,
                               const float* __restrict__ w)
{
    int n = blockIdx.x;
    int t = threadIdx.x;
    const float* hp = hin + (size_t)n * F_DIM;
    float s = 0.f;
    #pragma unroll 4
    for (int i = t; i < F_DIM; i += 256) s += hp[i] * w[i];
    __shared__ float sm[256];
    sm[t] = s;
    __syncthreads();
    for (int o = 128; o; o >>= 1) {
        if (t < o) sm[t] += sm[t + o];
        __syncthreads();
    }
    if (t == 0) g_nodeval[n] = sm[0];
}

__global__ void pool_kernel(const int* __restrict__ batch,
                            const float* __restrict__ lin_b,
                            float* __restrict__ out)
{
    __shared__ float ssum[G_GRAPHS];
    __shared__ int scnt[G_GRAPHS];
    int t = threadIdx.x;
    if (t < G_GRAPHS) { ssum[t] = 0.f; scnt[t] = 0; }
    __syncthreads();
    int g = batch[t];
    atomicAdd(&ssum[g], g_nodeval[t]);
    atomicAdd(&scnt[g], 1);
    __syncthreads();
    if (t < G_GRAPHS)
        out[t] = ssum[t] / fmaxf((float)scnt[t], 1.0f) + lin_b[0];
}

// ---------------- launch --------------------------------------------------------
extern "C" void kernel_launch(void* const* d_in, const int* in_sizes, int n_in,
                              void* d_out, int out_size)
{
    const float* x   = (const float*)d_in[0];
    const int*   ei  = (const int*)d_in[1];
    const int*   bat = (const int*)d_in[2];
    const float* W1  = (const float*)d_in[3];
    const float* as1 = (const float*)d_in[4];
    const float* ad1 = (const float*)d_in[5];
    const float* b1  = (const float*)d_in[6];
    const float* W2  = (const float*)d_in[7];
    const float* as2 = (const float*)d_in[8];
    const float* ad2 = (const float*)d_in[9];
    const float* b2  = (const float*)d_in[10];
    const float* lw  = (const float*)d_in[11];
    const float* lb  = (const float*)d_in[12];
    float* out = (float*)d_out;

    float *p_h = nullptr, *p_agg = nullptr;
    __nv_bfloat16 *p_Ah = nullptr, *p_Al = nullptr, *p_Bth = nullptr, *p_Btl = nullptr;
    cudaGetSymbolAddress((void**)&p_h, g_h);
    cudaGetSymbolAddress((void**)&p_agg, g_agg);
    cudaGetSymbolAddress((void**)&p_Ah, g_Ah);
    cudaGetSymbolAddress((void**)&p_Al, g_Al);
    cudaGetSymbolAddress((void**)&p_Bth, g_Bth);
    cudaGetSymbolAddress((void**)&p_Btl, g_Btl);

    cudaFuncSetAttribute(mma_gemm_kernel,
                         cudaFuncAttributeMaxDynamicSharedMemorySize, GEMM_SMEM);

    const int ethreads = 256;
    const int eblocks = (ET + ethreads - 1) / ethreads;

    // CSR build
    zero_cnt_kernel<<<1, N_NODES>>>();
    build_edges_kernel<<<eblocks, ethreads>>>(ei);
    scan_kernel<<<1, N_NODES>>>();
    scatter_kernel<<<eblocks, ethreads>>>();

    dim3 ggrid(F_DIM / 128, N_NODES / 128);   // (64, 8)
    dim3 tb32(32, 32);

    // ---- layer 1 ----
    convA_kernel<<<dim3((KP1 + 255) / 256, N_NODES), 256>>>(x, IN_DIM, KP1, p_Ah, p_Al);
    convBt_kernel<<<dim3(KP1 / 32, F_DIM / 32), tb32>>>(W1, IN_DIM, KP1, p_Bth, p_Btl);
    mma_gemm_kernel<<<ggrid, 256, GEMM_SMEM>>>(p_Ah, p_Al, p_Bth, p_Btl, p_h, KP1, KP1 / 32);
    scores_kernel<<<N_NODES, 512>>>(p_h, as1, ad1);
    attn_kernel<<<N_NODES, 512>>>();
    agg_kernel<<<N_NODES, 256>>>(p_h, b1, p_agg);

    // ---- layer 2 ----
    convA_kernel<<<dim3(F_DIM / 256, N_NODES), 256>>>(p_agg, F_DIM, F_DIM, p_Ah, p_Al);
    convBt_kernel<<<dim3(F_DIM / 32, F_DIM / 32), tb32>>>(W2, F_DIM, F_DIM, p_Bth, p_Btl);
    mma_gemm_kernel<<<ggrid, 256, GEMM_SMEM>>>(p_Ah, p_Al, p_Bth, p_Btl, p_h, F_DIM, F_DIM / 32);
    scores_kernel<<<N_NODES, 512>>>(p_h, as2, ad2);
    attn_kernel<<<N_NODES, 512>>>();
    agg_kernel<<<N_NODES, 256>>>(p_h, b2, p_agg);

    // ---- readout ----
    nodedot_kernel<<<N_NODES, 256>>>(p_agg, lw);
    pool_kernel<<<1, N_NODES>>>(bat, lb, out);
}